// round 1
// baseline (speedup 1.0000x reference)
#include <cuda_runtime.h>
#include <cuda_bf16.h>
#include <cstdint>

// GridLayer.get_nh — adjacency neighborhood gather.
// Inputs (metadata order):
//   d_in[0] x                  [B, N, NV, E]  float32   (4, 65536, 1, 128)
//   d_in[1] adjc               [N, NH]        int32     (65536, 7)
//   d_in[2] adjc_mask_invalid  [N, NH]        bool      (65536, 7)
//   d_in[3] local_indices      [B, N]         int32     (4, 65536)
//   d_in[4] batch_sample_indices [B]          int32     (4,)
//   d_in[5] sampled_level      scalar         int32
// Outputs (flattened into d_out, float32):
//   x_nh [B, N, NH, NV, E]  then  mask [B, N, NH, NV]

#define NB 4
#define NN 65536
#define NHH 7
#define NE 128
#define N_LOG2 16

__global__ void __launch_bounds__(256)
gridlayer_gather_kernel(const float* __restrict__ x,
                        const int* __restrict__ adjc,
                        const unsigned char* __restrict__ adjm,
                        const int* __restrict__ li,
                        const int* __restrict__ bsi,
                        const int* __restrict__ lvl,
                        float* __restrict__ out_x,
                        float* __restrict__ out_mask) {
    // one warp per output row (b, n, h)
    const long long total_rows = (long long)NB * NN * NHH;
    long long warp = ((long long)blockIdx.x * blockDim.x + threadIdx.x) >> 5;
    int lane = threadIdx.x & 31;
    if (warp >= total_rows) return;

    int h  = (int)(warp % NHH);
    long long bn = warp / NHH;       // b*N + n
    int b  = (int)(bn >> N_LOG2);    // N = 65536 = 2^16

    // uniform-per-warp scalar loads (broadcast, L1-resident)
    int l = __ldg(&li[bn]);
    int a = __ldg(&adjc[(long long)l * NHH + h]);

    int level = (lvl != nullptr) ? __ldg(lvl) : 0;
    int pw = (level > 0) ? (1 << (2 * level)) : 1;   // 4^level
    int g = a - __ldg(&bsi[b]) * pw;

    // copy 128 floats: one float4 per lane, fully coalesced 512B
    const float4* __restrict__ src =
        (const float4*)(x + (((long long)b << N_LOG2) + g) * NE);
    float4* __restrict__ dst = (float4*)(out_x + warp * (long long)NE);
    dst[lane] = __ldg(&src[lane]);

    if (lane == 0) {
        out_mask[warp] = (float)(__ldg(&adjm[(long long)l * NHH + h]) != 0);
    }
}

extern "C" void kernel_launch(void* const* d_in, const int* in_sizes, int n_in,
                              void* d_out, int out_size) {
    const float* x          = (const float*)d_in[0];
    const int* adjc         = (const int*)d_in[1];
    const unsigned char* am = (const unsigned char*)d_in[2];
    const int* li           = (const int*)d_in[3];
    const int* bsi          = (const int*)d_in[4];
    const int* lvl          = (n_in >= 6) ? (const int*)d_in[5] : nullptr;

    float* out_x = (float*)d_out;
    const long long rows = (long long)NB * NN * NHH;        // 1,835,008
    float* out_mask = out_x + rows * NE;                    // mask after x_nh

    // 8 warps per block of 256 threads; 1 warp per row
    long long warps = rows;
    int threads = 256;
    long long blocks = (warps * 32 + threads - 1) / threads;
    gridlayer_gather_kernel<<<(unsigned)blocks, threads>>>(
        x, adjc, am, li, bsi, lvl, out_x, out_mask);
}

// round 2
// speedup vs baseline: 1.9816x; 1.9816x over previous
#include <cuda_runtime.h>
#include <cuda_bf16.h>
#include <cstdint>

// GridLayer.get_nh — adjacency neighborhood gather.
// Inputs (metadata order):
//   d_in[0] x                  [B, N, NV, E]  float32   (4, 65536, 1, 128)
//   d_in[1] adjc               [N, NH]        int32     (65536, 7)
//   d_in[2] adjc_mask_invalid  [N, NH]        bool      (65536, 7)
//   d_in[3] local_indices      [B, N]         int32     (4, 65536)
//   d_in[4] batch_sample_indices [B]          int32     (4,)
//   d_in[5] sampled_level      scalar         int32
// Outputs (flattened into d_out, float32):
//   x_nh [B, N, NH, NV, E]  then  mask [B, N, NH, NV]

#define NB 4
#define NN 65536
#define NHH 7
#define NE 128
#define N_LOG2 16

__global__ void __launch_bounds__(256)
gridlayer_gather_kernel(const float* __restrict__ x,
                        const int* __restrict__ adjc,
                        const unsigned char* __restrict__ adjm,
                        const int* __restrict__ li,
                        const int* __restrict__ bsi,
                        const int* __restrict__ lvl,
                        float* __restrict__ out_x,
                        float* __restrict__ out_mask) {
    // one warp per (b, n) cell; handles all NHH=7 neighbors
    const long long total_cells = (long long)NB * NN;
    long long cell = ((long long)blockIdx.x * blockDim.x + threadIdx.x) >> 5;
    int lane = threadIdx.x & 31;
    if (cell >= total_cells) return;

    int b = (int)(cell >> N_LOG2);   // N = 65536 = 2^16

    // uniform-per-warp scalar loads (L1 broadcast)
    int l = __ldg(&li[cell]);
    int level = (lvl != nullptr) ? __ldg(lvl) : 0;
    int off = __ldg(&bsi[b]) * ((level > 0) ? (1 << (2 * level)) : 1);

    const int* __restrict__ arow = adjc + (long long)l * NHH;
    int g[NHH];
#pragma unroll
    for (int h = 0; h < NHH; h++)
        g[h] = __ldg(&arow[h]) - off;

    // 7 independent 512B gather loads (one float4 per lane per row): MLP=7
    const float4* __restrict__ xb =
        (const float4*)(x + ((long long)b << N_LOG2) * NE);
    float4 v[NHH];
#pragma unroll
    for (int h = 0; h < NHH; h++)
        v[h] = __ldg(&xb[(long long)g[h] * (NE / 4) + lane]);

    // contiguous 3.5KB store per warp; evict-first to keep L2 for x reuse
    float4* __restrict__ dst =
        (float4*)out_x + cell * (long long)(NHH * NE / 4) + lane;
#pragma unroll
    for (int h = 0; h < NHH; h++)
        __stcs(&dst[h * (NE / 4)], v[h]);

    // mask: lanes 0..6 write the 7 mask elements for this cell
    if (lane < NHH) {
        out_mask[cell * NHH + lane] =
            (float)(__ldg(&adjm[(long long)l * NHH + lane]) != 0);
    }
}

extern "C" void kernel_launch(void* const* d_in, const int* in_sizes, int n_in,
                              void* d_out, int out_size) {
    const float* x          = (const float*)d_in[0];
    const int* adjc         = (const int*)d_in[1];
    const unsigned char* am = (const unsigned char*)d_in[2];
    const int* li           = (const int*)d_in[3];
    const int* bsi          = (const int*)d_in[4];
    const int* lvl          = (n_in >= 6) ? (const int*)d_in[5] : nullptr;

    float* out_x = (float*)d_out;
    const long long rows = (long long)NB * NN * NHH;        // 1,835,008
    float* out_mask = out_x + rows * NE;                    // mask after x_nh

    const long long cells = (long long)NB * NN;             // 262,144 warps
    int threads = 256;
    long long blocks = (cells * 32 + threads - 1) / threads;
    gridlayer_gather_kernel<<<(unsigned)blocks, threads>>>(
        x, adjc, am, li, bsi, lvl, out_x, out_mask);
}

// round 3
// speedup vs baseline: 1.9919x; 1.0052x over previous
#include <cuda_runtime.h>
#include <cuda_bf16.h>
#include <cstdint>

// GridLayer.get_nh — adjacency neighborhood gather.
// Inputs (metadata order):
//   d_in[0] x                  [B, N, NV, E]  float32   (4, 65536, 1, 128)
//   d_in[1] adjc               [N, NH]        int32     (65536, 7)
//   d_in[2] adjc_mask_invalid  [N, NH]        bool      (65536, 7)
//   d_in[3] local_indices      [B, N]         int32     (4, 65536)
//   d_in[4] batch_sample_indices [B]          int32     (4,)
//   d_in[5] sampled_level      scalar         int32
// Outputs (flattened into d_out, float32):
//   x_nh [B, N, NH, NV, E]  then  mask [B, N, NH, NV]

#define NB 4
#define NN 65536
#define NHH 7
#define NE 128
#define N_LOG2 16

// L2-only 128-bit load (skip L1: random gather has ~0% L1 hit rate,
// don't burn L1 tag/wavefront bandwidth on it)
static __device__ __forceinline__ float4 ldcg128(const float4* p) {
    float4 v;
    asm volatile("ld.global.cg.v4.f32 {%0,%1,%2,%3}, [%4];"
                 : "=f"(v.x), "=f"(v.y), "=f"(v.z), "=f"(v.w)
                 : "l"(p));
    return v;
}

// evict-first 128-bit store (streaming output, keep L2 for x reuse)
static __device__ __forceinline__ void stcs128(float4* p, float4 v) {
    asm volatile("st.global.cs.v4.f32 [%0], {%1,%2,%3,%4};"
                 :: "l"(p), "f"(v.x), "f"(v.y), "f"(v.z), "f"(v.w));
}

__global__ void __launch_bounds__(256)
gridlayer_gather_kernel(const float* __restrict__ x,
                        const int* __restrict__ adjc,
                        const unsigned char* __restrict__ adjm,
                        const int* __restrict__ li,
                        const int* __restrict__ bsi,
                        const int* __restrict__ lvl,
                        float* __restrict__ out_x,
                        float* __restrict__ out_mask) {
    // one warp per (b, n) cell; handles all NHH=7 neighbors
    const long long total_cells = (long long)NB * NN;
    long long cell = ((long long)blockIdx.x * blockDim.x + threadIdx.x) >> 5;
    int lane = threadIdx.x & 31;
    if (cell >= total_cells) return;

    int b = (int)(cell >> N_LOG2);   // N = 65536 = 2^16

    // uniform-per-warp scalar loads (L1 broadcast)
    int l = __ldg(&li[cell]);
    int level = (lvl != nullptr) ? __ldg(lvl) : 0;
    int off = __ldg(&bsi[b]) * ((level > 0) ? (1 << (2 * level)) : 1);

    const int* __restrict__ arow = adjc + (long long)l * NHH;
    int g[NHH];
#pragma unroll
    for (int h = 0; h < NHH; h++)
        g[h] = __ldg(&arow[h]) - off;

    // 7 independent 512B gather loads, all issued as one front batch (MLP=7)
    const float4* __restrict__ xb =
        (const float4*)(x + ((long long)b << N_LOG2) * NE);
    float4 v[NHH];
#pragma unroll
    for (int h = 0; h < NHH; h++)
        v[h] = ldcg128(&xb[(long long)g[h] * (NE / 4) + lane]);

    // contiguous 3.5KB store per warp; evict-first to keep L2 for x reuse
    float4* __restrict__ dst =
        (float4*)out_x + cell * (long long)(NHH * NE / 4) + lane;
#pragma unroll
    for (int h = 0; h < NHH; h++)
        stcs128(&dst[h * (NE / 4)], v[h]);

    // mask: lanes 0..6 write the 7 mask elements for this cell
    if (lane < NHH) {
        out_mask[cell * NHH + lane] =
            (float)(__ldg(&adjm[(long long)l * NHH + lane]) != 0);
    }
}

extern "C" void kernel_launch(void* const* d_in, const int* in_sizes, int n_in,
                              void* d_out, int out_size) {
    const float* x          = (const float*)d_in[0];
    const int* adjc         = (const int*)d_in[1];
    const unsigned char* am = (const unsigned char*)d_in[2];
    const int* li           = (const int*)d_in[3];
    const int* bsi          = (const int*)d_in[4];
    const int* lvl          = (n_in >= 6) ? (const int*)d_in[5] : nullptr;

    float* out_x = (float*)d_out;
    const long long rows = (long long)NB * NN * NHH;        // 1,835,008
    float* out_mask = out_x + rows * NE;                    // mask after x_nh

    const long long cells = (long long)NB * NN;             // 262,144 warps
    int threads = 256;
    long long blocks = (cells * 32 + threads - 1) / threads;
    gridlayer_gather_kernel<<<(unsigned)blocks, threads>>>(
        x, adjc, am, li, bsi, lvl, out_x, out_mask);
}